// round 16
// baseline (speedup 1.0000x reference)
#include <cuda_runtime.h>
#include <cuda_fp16.h>
#include <cstdint>

// FeatureDictionary — fp16 codebook + 2 points/thread gather (6 in-flight
// one-line gathers per thread at ~half the register payload of f32).
//  P: merged prepass — f32->fp16 codebook convert + face int4 table
//  K: fused 4:1 block-specialized kernel
//     gather blocks: 8 lanes/pt, 2 pts/thread (stride-4 pairing), fp16 rows
//     tail blocks:   normal + coords_feats streaming
//  0 coords [B,S,3] f32   1 idx [B] i32         2 smpl_F [13776,3] i32
//  3 fid [B,S] i32        4 weights [B,S,3] f32  5 sdf [B,S,1] f32
//  6 hitpt [B,S,3] f32    7 codebooks [256,6890,64] f32
// Output: concat( weighted_feats [B,S,64], coords_feats [B,S,3], normal [B,S,3] )

#define NUM_VERTICES 6890
#define NUM_FACES_MAX 16384
#define DFEAT 64
#define MAXB 8
#define CB_U2 (NUM_VERTICES * DFEAT / 4)

__device__ int4   g_faceVerts[NUM_FACES_MAX];
__device__ __half g_cbh[MAXB * NUM_VERTICES * DFEAT];   // 7MB fp16 scratch

__global__ __launch_bounds__(256)
void prepass_kernel(const int* __restrict__ idx,
                    const float* __restrict__ codebooks,
                    const int* __restrict__ smpl_F,
                    int B, int nFaces)
{
    int t = blockIdx.x * blockDim.x + threadIdx.x;
    int convTotal = B * CB_U2;

    if (t < convTotal) {
        int b = t / CB_U2;
        int u = t - b * CB_U2;
        int subj = __ldg(idx + b);
        const float4* src = (const float4*)(codebooks
                            + (size_t)subj * (NUM_VERTICES * DFEAT));
        uint2* dst = (uint2*)(g_cbh + (size_t)b * (NUM_VERTICES * DFEAT));
        float4 v = __ldcs(src + u);
        __half2 lo = __floats2half2_rn(v.x, v.y);
        __half2 hi = __floats2half2_rn(v.z, v.w);
        uint2 o;
        o.x = *(unsigned*)&lo;
        o.y = *(unsigned*)&hi;
        dst[u] = o;
    } else {
        int ft = t - convTotal;
        if (ft < nFaces) {
            int v0 = __ldg(smpl_F + 3 * ft + 0);
            int v1 = __ldg(smpl_F + 3 * ft + 1);
            int v2 = __ldg(smpl_F + 3 * ft + 2);
            g_faceVerts[ft] = make_int4(v0, v1, v2, 0);
        }
    }
}

__device__ __forceinline__ void fma8(float* o, float w, uint4 R)
{
    float2 x0 = __half22float2(*(__half2*)&R.x);
    float2 x1 = __half22float2(*(__half2*)&R.y);
    float2 x2 = __half22float2(*(__half2*)&R.z);
    float2 x3 = __half22float2(*(__half2*)&R.w);
    o[0] += w * x0.x;  o[1] += w * x0.y;
    o[2] += w * x1.x;  o[3] += w * x1.y;
    o[4] += w * x2.x;  o[5] += w * x2.y;
    o[6] += w * x3.x;  o[7] += w * x3.y;
}

__global__ __launch_bounds__(256)
void fused_kernel(const float* __restrict__ coords,
                  const int*   __restrict__ fid,
                  const float* __restrict__ weights,
                  const float* __restrict__ sdf,
                  const float* __restrict__ hitpt,
                  float*       __restrict__ out,
                  int BS, int S, int Sshift)
{
    // Block-type decode: every 5th block (r==4) is a tail block.
    int blk = blockIdx.x;
    int q   = blk / 5;
    int r   = blk - q * 5;

    if (r == 4) {
        int p = q * 256 + threadIdx.x;
        if (p >= BS) return;

        size_t C_OFF = (size_t)BS * DFEAT;
        size_t N_OFF = C_OFF + (size_t)BS * 3;

        float cx = __ldcs(coords + 3 * p + 0);
        float cy = __ldcs(coords + 3 * p + 1);
        float cz = __ldcs(coords + 3 * p + 2);
        float hx = __ldcs(hitpt  + 3 * p + 0);
        float hy = __ldcs(hitpt  + 3 * p + 1);
        float hz = __ldcs(hitpt  + 3 * p + 2);
        float w1 = __ldcs(weights + 3 * p + 1);
        float w2 = __ldcs(weights + 3 * p + 2);
        float sd = __ldcs(sdf + p);

        float dx = hx - cx, dy = hy - cy, dz = hz - cz;
        float nrm = sqrtf(dx * dx + dy * dy + dz * dz);
        float inv = 1.0f / fmaxf(nrm, 1e-6f);

        __stcs(out + N_OFF + 3 * (size_t)p + 0, dx * inv);
        __stcs(out + N_OFF + 3 * (size_t)p + 1, dy * inv);
        __stcs(out + N_OFF + 3 * (size_t)p + 2, dz * inv);
        __stcs(out + C_OFF + 3 * (size_t)p + 0, w1);
        __stcs(out + C_OFF + 3 * (size_t)p + 1, w2);
        __stcs(out + C_OFF + 3 * (size_t)p + 2, sd);
        return;
    }

    // ---- gather path: 8 lanes/pt, 2 pts/thread (stride-4 pairing) ----
    int gblk = q * 4 + r;
    int L    = gblk * 256 + threadIdx.x;
    int w    = L >> 5;            // global warp index: 8 consecutive points
    int slot = (L >> 3) & 3;
    int lane = L & 7;

    int pA = w * 8 + slot;        // global point indices
    int pB = pA + 4;
    if (pA >= BS) return;
    bool hasB = (pB < BS);

    int bA = (Sshift >= 0) ? (pA >> Sshift) : (pA / S);
    const __half* cbA = g_cbh + (size_t)bA * (NUM_VERTICES * DFEAT);

    // ctx A
    int fA = __ldcs(fid + pA);
    int4 vA = __ldg(&g_faceVerts[fA]);
    float wA0 = __ldcs(weights + 3 * pA + 0);
    float wA1 = __ldcs(weights + 3 * pA + 1);
    float wA2 = __ldcs(weights + 3 * pA + 2);

    // Issue A gathers (3 one-line loads).
    uint4 A0 = __ldg((const uint4*)(cbA + (size_t)vA.x * DFEAT) + lane);
    uint4 A1 = __ldg((const uint4*)(cbA + (size_t)vA.y * DFEAT) + lane);
    uint4 A2 = __ldg((const uint4*)(cbA + (size_t)vA.z * DFEAT) + lane);

    // ctx B + B gathers while A's are in flight.
    uint4 B0, B1, B2;
    float wB0 = 0.f, wB1 = 0.f, wB2 = 0.f;
    if (hasB) {
        int bB = (Sshift >= 0) ? (pB >> Sshift) : (pB / S);
        const __half* cbB = g_cbh + (size_t)bB * (NUM_VERTICES * DFEAT);
        int fB = __ldcs(fid + pB);
        int4 vB = __ldg(&g_faceVerts[fB]);
        wB0 = __ldcs(weights + 3 * pB + 0);
        wB1 = __ldcs(weights + 3 * pB + 1);
        wB2 = __ldcs(weights + 3 * pB + 2);
        B0 = __ldg((const uint4*)(cbB + (size_t)vB.x * DFEAT) + lane);
        B1 = __ldg((const uint4*)(cbB + (size_t)vB.y * DFEAT) + lane);
        B2 = __ldg((const uint4*)(cbB + (size_t)vB.z * DFEAT) + lane);
    }

    // Consume A.
    {
        float o[8] = {0,0,0,0,0,0,0,0};
        fma8(o, wA0, A0);
        fma8(o, wA1, A1);
        fma8(o, wA2, A2);
        float4* outv = (float4*)out + (size_t)pA * (DFEAT / 4) + 2 * lane;
        __stcs(outv,     make_float4(o[0], o[1], o[2], o[3]));
        __stcs(outv + 1, make_float4(o[4], o[5], o[6], o[7]));
    }

    // Consume B.
    if (hasB) {
        float o[8] = {0,0,0,0,0,0,0,0};
        fma8(o, wB0, B0);
        fma8(o, wB1, B1);
        fma8(o, wB2, B2);
        float4* outv = (float4*)out + (size_t)pB * (DFEAT / 4) + 2 * lane;
        __stcs(outv,     make_float4(o[0], o[1], o[2], o[3]));
        __stcs(outv + 1, make_float4(o[4], o[5], o[6], o[7]));
    }
}

extern "C" void kernel_launch(void* const* d_in, const int* in_sizes, int n_in,
                              void* d_out, int out_size)
{
    const float* coords    = (const float*)d_in[0];
    const int*   idx       = (const int*)  d_in[1];
    const int*   smpl_F    = (const int*)  d_in[2];
    const int*   fid       = (const int*)  d_in[3];
    const float* weights   = (const float*)d_in[4];
    const float* sdf       = (const float*)d_in[5];
    const float* hitpt     = (const float*)d_in[6];
    const float* codebooks = (const float*)d_in[7];
    float*       out       = (float*)d_out;

    int BS = in_sizes[3];       // B*S
    int B  = in_sizes[1];       // batch
    int S  = BS / B;
    int nFaces = in_sizes[2] / 3;

    int Sshift = -1;
    if ((S & (S - 1)) == 0) {
        Sshift = 0;
        while ((1 << Sshift) < S) Sshift++;
    }

    // P: merged prepass (convert + face table).
    long long prework = (long long)B * CB_U2 + nFaces;
    prepass_kernel<<<(unsigned)((prework + 255) / 256), 256>>>(
        idx, codebooks, smpl_F, B, nFaces);

    // K: fused gather+tail, 4:1 interleave (gather thread covers 2 points).
    int NB = (BS + 255) / 256;
    long long NA = ((long long)BS * 4 + 255) / 256;
    long long total = NA + NB;

    fused_kernel<<<(unsigned)total, 256>>>(
        coords, fid, weights, sdf, hitpt, out, BS, S, Sshift);
}

// round 17
// speedup vs baseline: 1.1688x; 1.1688x over previous
#include <cuda_runtime.h>
#include <cuda_fp16.h>
#include <cstdint>

// FeatureDictionary — fp16 codebook with LANE-PERMUTED row layout.
// Permutation: lane l's uint4 (8 halves) = features {4l..4l+3, 4l+32..4l+35}.
//  -> gather: 3 one-line (128B) loads per point     (12 wavefronts/warp)
//  -> store:  2 contiguous-128B float4 instrs       ( 8 wavefronts/warp)
//  P: merged prepass — permuted f32->fp16 convert + face int4 table
//  K: fused 8:1 block-specialized kernel (gather / tail)
//  0 coords [B,S,3] f32   1 idx [B] i32         2 smpl_F [13776,3] i32
//  3 fid [B,S] i32        4 weights [B,S,3] f32  5 sdf [B,S,1] f32
//  6 hitpt [B,S,3] f32    7 codebooks [256,6890,64] f32
// Output: concat( weighted_feats [B,S,64], coords_feats [B,S,3], normal [B,S,3] )

#define NUM_VERTICES 6890
#define NUM_FACES_MAX 16384
#define DFEAT 64
#define MAXB 8
#define CB_U2 (NUM_VERTICES * DFEAT / 4)   // float4 convert units per subject

__device__ int4   g_faceVerts[NUM_FACES_MAX];
__device__ __half g_cbh[MAXB * NUM_VERTICES * DFEAT];   // 7MB fp16 scratch

// Merged prepass. Convert unit u = one float4 (features j..j+3 of one row),
// written to the PERMUTED position: lane = (j<32 ? j : j-32)/4,
// halfoff = lane*8 + (j<32 ? 0 : 4).
__global__ __launch_bounds__(256)
void prepass_kernel(const int* __restrict__ idx,
                    const float* __restrict__ codebooks,
                    const int* __restrict__ smpl_F,
                    int B, int nFaces)
{
    int t = blockIdx.x * blockDim.x + threadIdx.x;
    int convTotal = B * CB_U2;

    if (t < convTotal) {
        int b = t / CB_U2;
        int u = t - b * CB_U2;
        int row = u >> 4;               // vertex row
        int j   = (u & 15) << 2;        // feature index (multiple of 4)
        int subj = __ldg(idx + b);
        const float4* src = (const float4*)(codebooks
                            + (size_t)subj * (NUM_VERTICES * DFEAT));
        float4 v = __ldcs(src + u);
        __half2 lo = __floats2half2_rn(v.x, v.y);
        __half2 hi = __floats2half2_rn(v.z, v.w);
        uint2 o;
        o.x = *(unsigned*)&lo;
        o.y = *(unsigned*)&hi;

        int lane    = ((j < 32) ? j : (j - 32)) >> 2;
        int halfoff = lane * 8 + ((j < 32) ? 0 : 4);
        uint2* dst = (uint2*)(g_cbh + (size_t)b * (NUM_VERTICES * DFEAT)
                              + (size_t)row * DFEAT + halfoff);
        *dst = o;
    } else {
        int ft = t - convTotal;
        if (ft < nFaces) {
            int v0 = __ldg(smpl_F + 3 * ft + 0);
            int v1 = __ldg(smpl_F + 3 * ft + 1);
            int v2 = __ldg(smpl_F + 3 * ft + 2);
            g_faceVerts[ft] = make_int4(v0, v1, v2, 0);
        }
    }
}

__device__ __forceinline__ void fma8(float* o, float w, uint4 R)
{
    float2 x0 = __half22float2(*(__half2*)&R.x);
    float2 x1 = __half22float2(*(__half2*)&R.y);
    float2 x2 = __half22float2(*(__half2*)&R.z);
    float2 x3 = __half22float2(*(__half2*)&R.w);
    o[0] += w * x0.x;  o[1] += w * x0.y;
    o[2] += w * x1.x;  o[3] += w * x1.y;
    o[4] += w * x2.x;  o[5] += w * x2.y;
    o[6] += w * x3.x;  o[7] += w * x3.y;
}

__global__ __launch_bounds__(256)
void fused_kernel(const float* __restrict__ coords,
                  const int*   __restrict__ fid,
                  const float* __restrict__ weights,
                  const float* __restrict__ sdf,
                  const float* __restrict__ hitpt,
                  float*       __restrict__ out,
                  int BS, int S, int Sshift)
{
    // Block-type decode: every 9th block (r==8) is a tail block.
    int blk = blockIdx.x;
    int q   = blk / 9;
    int r   = blk - q * 9;

    if (r == 8) {
        int p = q * 256 + threadIdx.x;
        if (p >= BS) return;

        size_t C_OFF = (size_t)BS * DFEAT;
        size_t N_OFF = C_OFF + (size_t)BS * 3;

        float cx = __ldcs(coords + 3 * p + 0);
        float cy = __ldcs(coords + 3 * p + 1);
        float cz = __ldcs(coords + 3 * p + 2);
        float hx = __ldcs(hitpt  + 3 * p + 0);
        float hy = __ldcs(hitpt  + 3 * p + 1);
        float hz = __ldcs(hitpt  + 3 * p + 2);
        float w1 = __ldcs(weights + 3 * p + 1);
        float w2 = __ldcs(weights + 3 * p + 2);
        float sd = __ldcs(sdf + p);

        float dx = hx - cx, dy = hy - cy, dz = hz - cz;
        float nrm = sqrtf(dx * dx + dy * dy + dz * dz);
        float inv = 1.0f / fmaxf(nrm, 1e-6f);

        __stcs(out + N_OFF + 3 * (size_t)p + 0, dx * inv);
        __stcs(out + N_OFF + 3 * (size_t)p + 1, dy * inv);
        __stcs(out + N_OFF + 3 * (size_t)p + 2, dz * inv);
        __stcs(out + C_OFF + 3 * (size_t)p + 0, w1);
        __stcs(out + C_OFF + 3 * (size_t)p + 1, w2);
        __stcs(out + C_OFF + 3 * (size_t)p + 2, sd);
        return;
    }

    // ---- gather path: 8 lanes per point, permuted fp16 rows ----
    int gblk = q * 8 + r;
    int L    = gblk * 256 + threadIdx.x;
    int p    = L >> 3;
    int lane = L & 7;
    if (p >= BS) return;

    int b = (Sshift >= 0) ? (p >> Sshift) : (p / S);
    const __half* cb = g_cbh + (size_t)b * (NUM_VERTICES * DFEAT);

    int f = __ldcs(fid + p);
    int4 v = __ldg(&g_faceVerts[f]);

    float w0 = __ldcs(weights + 3 * p + 0);
    float w1 = __ldcs(weights + 3 * p + 1);
    float w2 = __ldcs(weights + 3 * p + 2);

    // One 16B load per row per lane (permuted features).
    uint4 A = __ldg((const uint4*)(cb + (size_t)v.x * DFEAT) + lane);
    uint4 C = __ldg((const uint4*)(cb + (size_t)v.y * DFEAT) + lane);
    uint4 D = __ldg((const uint4*)(cb + (size_t)v.z * DFEAT) + lane);

    float o[8] = {0,0,0,0,0,0,0,0};
    fma8(o, w0, A);
    fma8(o, w1, C);
    fma8(o, w2, D);

    // o[0..3] = feats[4*lane .. +4), o[4..7] = feats[32+4*lane .. +4):
    // both stores are contiguous 128B per point -> 1 wavefront each.
    float4* outv = (float4*)out + (size_t)p * (DFEAT / 4);
    __stcs(outv + lane,     make_float4(o[0], o[1], o[2], o[3]));
    __stcs(outv + 8 + lane, make_float4(o[4], o[5], o[6], o[7]));
}

extern "C" void kernel_launch(void* const* d_in, const int* in_sizes, int n_in,
                              void* d_out, int out_size)
{
    const float* coords    = (const float*)d_in[0];
    const int*   idx       = (const int*)  d_in[1];
    const int*   smpl_F    = (const int*)  d_in[2];
    const int*   fid       = (const int*)  d_in[3];
    const float* weights   = (const float*)d_in[4];
    const float* sdf       = (const float*)d_in[5];
    const float* hitpt     = (const float*)d_in[6];
    const float* codebooks = (const float*)d_in[7];
    float*       out       = (float*)d_out;

    int BS = in_sizes[3];       // B*S
    int B  = in_sizes[1];       // batch
    int S  = BS / B;
    int nFaces = in_sizes[2] / 3;

    int Sshift = -1;
    if ((S & (S - 1)) == 0) {
        Sshift = 0;
        while ((1 << Sshift) < S) Sshift++;
    }

    // P: merged prepass (permuted convert + face table).
    long long prework = (long long)B * CB_U2 + nFaces;
    prepass_kernel<<<(unsigned)((prework + 255) / 256), 256>>>(
        idx, codebooks, smpl_F, B, nFaces);

    // K: fused gather+tail, 8:1 interleave.
    int NB = (BS + 255) / 256;
    long long NA = ((long long)BS * 8 + 255) / 256;
    long long total = NA + NB;

    fused_kernel<<<(unsigned)total, 256>>>(
        coords, fid, weights, sdf, hitpt, out, BS, S, Sshift);
}